// round 3
// baseline (speedup 1.0000x reference)
#include <cuda_runtime.h>
#include <cuda_bf16.h>
#include <cstdint>

// Problem constants (from reference)
#define N_NODES 100000
#define D 512        // D_IN == D_OUT == 512

// Scratch for projected features hp = h @ W  (204.8 MB, static device alloc)
__device__ float g_hp[(size_t)N_NODES * D];

// ---------------------------------------------------------------------------
// Kernel 1: fp32 tiled GEMM  hp[M,512] = h[M,512] @ W[512,512]
// BM=BN=64, BK=16, 256 threads (16x16), each thread computes 4x4.
// ---------------------------------------------------------------------------
__global__ __launch_bounds__(256) void gemm_kernel(
    const float* __restrict__ h,
    const float* __restrict__ w,
    float* __restrict__ hp,
    int M)
{
    __shared__ float As[16][65];   // padded: conflict-free transposed stores
    __shared__ float Bs[16][64];

    const int tid = threadIdx.x;
    const int tx = tid & 15;       // 0..15 -> output col group
    const int ty = tid >> 4;       // 0..15 -> output row group

    const int n0 = blockIdx.x * 64;
    const int m0 = blockIdx.y * 64;

    float c[4][4];
    #pragma unroll
    for (int i = 0; i < 4; i++)
        #pragma unroll
        for (int j = 0; j < 4; j++) c[i][j] = 0.0f;

    for (int kt = 0; kt < D; kt += 16) {
        // Load A tile: 64 rows x 16 k  (store transposed: As[k][m])
        #pragma unroll
        for (int l = 0; l < 4; l++) {
            int e = tid + l * 256;          // 0..1023
            int m = e >> 4;                 // 0..63
            int k = e & 15;                 // 0..15
            int gm = m0 + m;
            As[k][m] = (gm < M) ? h[(size_t)gm * D + kt + k] : 0.0f;
        }
        // Load B tile: 16 k x 64 n (coalesced)
        #pragma unroll
        for (int l = 0; l < 4; l++) {
            int e = tid + l * 256;
            int k = e >> 6;                 // 0..15
            int n = e & 63;                 // 0..63
            Bs[k][n] = w[(size_t)(kt + k) * D + n0 + n];
        }
        __syncthreads();

        #pragma unroll
        for (int k = 0; k < 16; k++) {
            float a0 = As[k][ty * 4 + 0];
            float a1 = As[k][ty * 4 + 1];
            float a2 = As[k][ty * 4 + 2];
            float a3 = As[k][ty * 4 + 3];
            float4 b = *reinterpret_cast<const float4*>(&Bs[k][tx * 4]);
            c[0][0] += a0 * b.x; c[0][1] += a0 * b.y; c[0][2] += a0 * b.z; c[0][3] += a0 * b.w;
            c[1][0] += a1 * b.x; c[1][1] += a1 * b.y; c[1][2] += a1 * b.z; c[1][3] += a1 * b.w;
            c[2][0] += a2 * b.x; c[2][1] += a2 * b.y; c[2][2] += a2 * b.z; c[2][3] += a2 * b.w;
            c[3][0] += a3 * b.x; c[3][1] += a3 * b.y; c[3][2] += a3 * b.z; c[3][3] += a3 * b.w;
        }
        __syncthreads();
    }

    // Store 4x4 per thread (float4 per row)
    #pragma unroll
    for (int i = 0; i < 4; i++) {
        int gm = m0 + ty * 4 + i;
        if (gm < M) {
            float4 v = make_float4(c[i][0], c[i][1], c[i][2], c[i][3]);
            *reinterpret_cast<float4*>(&hp[(size_t)gm * D + n0 + tx * 4]) = v;
        }
    }
}

// ---------------------------------------------------------------------------
// Kernel 2: edge scatter — one warp per edge.
// out[dst] += hp[src] * ew  via vector red.global.add.v4.f32
// NOTE: src/dst are int32 (JAX x64-disabled silently downgrades int64).
// ---------------------------------------------------------------------------
__global__ __launch_bounds__(256) void scatter_kernel(
    const float* __restrict__ hp,
    const float* __restrict__ ew,
    const int* __restrict__ src,
    const int* __restrict__ dst,
    float* __restrict__ out,
    int E)
{
    int gwarp = (blockIdx.x * blockDim.x + threadIdx.x) >> 5;
    int lane = threadIdx.x & 31;
    if (gwarp >= E) return;

    int s = 0, d = 0;
    float w = 0.0f;
    if (lane == 0) {
        s = src[gwarp];
        d = dst[gwarp];
        w = ew[gwarp];
    }
    s = __shfl_sync(0xFFFFFFFFu, s, 0);
    d = __shfl_sync(0xFFFFFFFFu, d, 0);
    w = __shfl_sync(0xFFFFFFFFu, w, 0);

    const float4* srow = reinterpret_cast<const float4*>(hp + (size_t)s * D);
    float4* drow = reinterpret_cast<float4*>(out + (size_t)d * D);

    #pragma unroll
    for (int i = 0; i < 4; i++) {           // 4 * 32 lanes * 4 floats = 512
        float4 v = srow[lane + i * 32];
        v.x *= w; v.y *= w; v.z *= w; v.w *= w;
        float4* p = drow + lane + i * 32;
        asm volatile("red.global.add.v4.f32 [%0], {%1, %2, %3, %4};"
                     :: "l"(p), "f"(v.x), "f"(v.y), "f"(v.z), "f"(v.w)
                     : "memory");
    }
}

// ---------------------------------------------------------------------------
// Kernel 3: in-place ReLU on d_out
// ---------------------------------------------------------------------------
__global__ __launch_bounds__(256) void relu_kernel(float4* __restrict__ out, size_t n4)
{
    size_t i = (size_t)blockIdx.x * blockDim.x + threadIdx.x;
    size_t stride = (size_t)gridDim.x * blockDim.x;
    for (; i < n4; i += stride) {
        float4 v = out[i];
        v.x = fmaxf(v.x, 0.0f);
        v.y = fmaxf(v.y, 0.0f);
        v.z = fmaxf(v.z, 0.0f);
        v.w = fmaxf(v.w, 0.0f);
        out[i] = v;
    }
}

// ---------------------------------------------------------------------------
// Launch
// Inputs (metadata order): h [N*512] f32, weight [512*512] f32,
//                          edge_weight [E] f32, src [E] i32, dst [E] i32
// Output: [N*512] f32
// ---------------------------------------------------------------------------
extern "C" void kernel_launch(void* const* d_in, const int* in_sizes, int n_in,
                              void* d_out, int out_size)
{
    const float* h   = (const float*)d_in[0];
    const float* w   = (const float*)d_in[1];
    const float* ew  = (const float*)d_in[2];
    const int*   sv  = (const int*)d_in[3];
    const int*   dv  = (const int*)d_in[4];
    float* out       = (float*)d_out;

    const int M = in_sizes[0] / D;      // 100000
    const int E = in_sizes[2];          // 1600000

    static float* hp = nullptr;         // cached: resolve symbol once
    if (!hp) cudaGetSymbolAddress((void**)&hp, g_hp);

    // Zero the accumulator (graph-capturable memset node)
    cudaMemsetAsync(d_out, 0, (size_t)out_size * sizeof(float));

    // 1) hp = h @ W
    dim3 ggrid(D / 64, (M + 63) / 64);
    gemm_kernel<<<ggrid, 256>>>(h, w, hp, M);

    // 2) scatter-add: one warp per edge
    long long nthreads = (long long)E * 32;
    int sblocks = (int)((nthreads + 255) / 256);
    scatter_kernel<<<sblocks, 256>>>(hp, ew, sv, dv, out, E);

    // 3) ReLU in place
    size_t n4 = (size_t)out_size / 4;
    int rblocks = 148 * 12;
    relu_kernel<<<rblocks, 256>>>((float4*)out, n4);
}

// round 4
// speedup vs baseline: 1.3627x; 1.3627x over previous
#include <cuda_runtime.h>
#include <cuda_bf16.h>
#include <cstdint>

#define N_NODES 100000
#define D 512

// Scratch for projected features hp = h @ W  (204.8 MB, static device alloc)
__device__ float g_hp[(size_t)N_NODES * D];

// ---------------------------------------------------------------------------
// Helpers: tf32 split (truncation split: x = hi + lo, both tf32-representable)
// ---------------------------------------------------------------------------
__device__ __forceinline__ void split_tf32(float x, uint32_t& hi, uint32_t& lo)
{
    uint32_t xh = __float_as_uint(x) & 0xFFFFE000u;
    float fh = __uint_as_float(xh);
    float fl = x - fh;
    hi = xh;
    lo = __float_as_uint(fl) & 0xFFFFE000u;
}

__device__ __forceinline__ void mma_tf32(float c[4], const uint32_t a[4], const uint32_t b[2])
{
    asm volatile(
        "mma.sync.aligned.m16n8k8.row.col.f32.tf32.tf32.f32 "
        "{%0,%1,%2,%3}, {%4,%5,%6,%7}, {%8,%9}, {%0,%1,%2,%3};"
        : "+f"(c[0]), "+f"(c[1]), "+f"(c[2]), "+f"(c[3])
        : "r"(a[0]), "r"(a[1]), "r"(a[2]), "r"(a[3]), "r"(b[0]), "r"(b[1]));
}

#define CP_ASYNC16(dst_smem_u32, src_ptr) \
    asm volatile("cp.async.cg.shared.global [%0], [%1], 16;" \
                 :: "r"(dst_smem_u32), "l"(src_ptr))
#define CP_ASYNC_COMMIT() asm volatile("cp.async.commit_group;")
#define CP_ASYNC_WAIT0()  asm volatile("cp.async.wait_group 0;")

// ---------------------------------------------------------------------------
// Kernel 1: 3xTF32 tensor-core GEMM  hp[M,512] = h[M,512] @ W[512,512]
// BM=128, BN=64, BK=16. 256 threads = 8 warps (4 warp_m x 2 warp_n),
// warp tile 32x32 = 2 (m16) x 4 (n8) fragments. 2-stage cp.async pipeline.
// ---------------------------------------------------------------------------
__global__ __launch_bounds__(256) void gemm_tf32_kernel(
    const float* __restrict__ h,
    const float* __restrict__ w,
    float* __restrict__ hp,
    int M)
{
    // Padded strides chosen for conflict-free fragment loads:
    // A: stride 20 -> (20*g) mod 32 in {0,20,8,28,16,4,24,12} (distinct x4 +tig)
    // B: stride 72 -> (72*k) mod 32 = 8k in {0,8,16,24} (+gid 0..7 disjoint)
    __shared__ float As[2][128][20];
    __shared__ float Bs[2][16][72];

    const int tid  = threadIdx.x;
    const int wid  = tid >> 5;
    const int lane = tid & 31;
    const int gid  = lane >> 2;     // groupID 0..7
    const int tig  = lane & 3;      // thread-in-group 0..3

    const int warp_m = wid & 3;     // 0..3  (32 rows each)
    const int warp_n = wid >> 2;    // 0..1  (32 cols each)

    const int m0 = blockIdx.y * 128;
    const int n0 = blockIdx.x * 64;

    // Global load mapping
    const int arow = tid >> 2;          // 0..63
    const int acol = (tid & 3) * 4;     // 0,4,8,12
    const int brow = tid >> 4;          // 0..15
    const int bcol = (tid & 15) * 4;    // 0..60

    // clamp A rows (padding rows read row M-1; never stored)
    const int gmA0 = min(m0 + arow,      M - 1);
    const int gmA1 = min(m0 + arow + 64, M - 1);

    auto load_tile = [&](int stage, int kt) {
        const int kbase = kt * 16;
        uint32_t d0 = (uint32_t)__cvta_generic_to_shared(&As[stage][arow][acol]);
        uint32_t d1 = (uint32_t)__cvta_generic_to_shared(&As[stage][arow + 64][acol]);
        CP_ASYNC16(d0, h + (size_t)gmA0 * D + kbase + acol);
        CP_ASYNC16(d1, h + (size_t)gmA1 * D + kbase + acol);
        uint32_t d2 = (uint32_t)__cvta_generic_to_shared(&Bs[stage][brow][bcol]);
        CP_ASYNC16(d2, w + (size_t)(kbase + brow) * D + n0 + bcol);
        CP_ASYNC_COMMIT();
    };

    float c[2][4][4];
    #pragma unroll
    for (int mi = 0; mi < 2; mi++)
        #pragma unroll
        for (int ni = 0; ni < 4; ni++)
            #pragma unroll
            for (int r = 0; r < 4; r++) c[mi][ni][r] = 0.0f;

    // Prologue: load tile 0
    load_tile(0, 0);
    CP_ASYNC_WAIT0();
    __syncthreads();

    const int NK = D / 16;   // 32
    #pragma unroll 1
    for (int kt = 0; kt < NK; kt++) {
        const int s = kt & 1;
        if (kt + 1 < NK) load_tile(s ^ 1, kt + 1);

        #pragma unroll
        for (int ks = 0; ks < 2; ks++) {
            const int k0 = ks * 8;

            // A fragments (hi/lo)
            uint32_t ah[2][4], al[2][4];
            #pragma unroll
            for (int mi = 0; mi < 2; mi++) {
                const int mb = warp_m * 32 + mi * 16;
                float a0 = As[s][mb + gid    ][k0 + tig    ];
                float a1 = As[s][mb + gid + 8][k0 + tig    ];
                float a2 = As[s][mb + gid    ][k0 + tig + 4];
                float a3 = As[s][mb + gid + 8][k0 + tig + 4];
                split_tf32(a0, ah[mi][0], al[mi][0]);
                split_tf32(a1, ah[mi][1], al[mi][1]);
                split_tf32(a2, ah[mi][2], al[mi][2]);
                split_tf32(a3, ah[mi][3], al[mi][3]);
            }
            // B fragments (hi/lo)
            uint32_t bh[4][2], bl[4][2];
            #pragma unroll
            for (int ni = 0; ni < 4; ni++) {
                const int nb = warp_n * 32 + ni * 8;
                float b0 = Bs[s][k0 + tig    ][nb + gid];
                float b1 = Bs[s][k0 + tig + 4][nb + gid];
                split_tf32(b0, bh[ni][0], bl[ni][0]);
                split_tf32(b1, bh[ni][1], bl[ni][1]);
            }

            #pragma unroll
            for (int mi = 0; mi < 2; mi++)
                #pragma unroll
                for (int ni = 0; ni < 4; ni++) {
                    mma_tf32(c[mi][ni], ah[mi], bh[ni]);   // hi*hi
                    mma_tf32(c[mi][ni], ah[mi], bl[ni]);   // hi*lo
                    mma_tf32(c[mi][ni], al[mi], bh[ni]);   // lo*hi
                }
        }

        CP_ASYNC_WAIT0();
        __syncthreads();
    }

    // Epilogue: C frag (16x8): c0 (gid, 2*tig), c1 (gid, 2*tig+1),
    //                          c2 (gid+8, 2*tig), c3 (gid+8, 2*tig+1)
    #pragma unroll
    for (int mi = 0; mi < 2; mi++) {
        #pragma unroll
        for (int ni = 0; ni < 4; ni++) {
            const int mrow = m0 + warp_m * 32 + mi * 16 + gid;
            const int ncol = n0 + warp_n * 32 + ni * 8 + tig * 2;
            if (mrow < M) {
                float2 v = make_float2(c[mi][ni][0], c[mi][ni][1]);
                *reinterpret_cast<float2*>(&hp[(size_t)mrow * D + ncol]) = v;
            }
            if (mrow + 8 < M) {
                float2 v = make_float2(c[mi][ni][2], c[mi][ni][3]);
                *reinterpret_cast<float2*>(&hp[(size_t)(mrow + 8) * D + ncol]) = v;
            }
        }
    }
}

// ---------------------------------------------------------------------------
// Kernel 2: edge scatter — one warp per edge; red.global.add.v4.f32
// ---------------------------------------------------------------------------
__global__ __launch_bounds__(256) void scatter_kernel(
    const float* __restrict__ hp,
    const float* __restrict__ ew,
    const int* __restrict__ src,
    const int* __restrict__ dst,
    float* __restrict__ out,
    int E)
{
    int gwarp = (blockIdx.x * blockDim.x + threadIdx.x) >> 5;
    int lane = threadIdx.x & 31;
    if (gwarp >= E) return;

    int s = 0, d = 0;
    float w = 0.0f;
    if (lane == 0) {
        s = src[gwarp];
        d = dst[gwarp];
        w = ew[gwarp];
    }
    s = __shfl_sync(0xFFFFFFFFu, s, 0);
    d = __shfl_sync(0xFFFFFFFFu, d, 0);
    w = __shfl_sync(0xFFFFFFFFu, w, 0);

    const float4* srow = reinterpret_cast<const float4*>(hp + (size_t)s * D);
    float4* drow = reinterpret_cast<float4*>(out + (size_t)d * D);

    #pragma unroll
    for (int i = 0; i < 4; i++) {
        float4 v = srow[lane + i * 32];
        v.x *= w; v.y *= w; v.z *= w; v.w *= w;
        float4* p = drow + lane + i * 32;
        asm volatile("red.global.add.v4.f32 [%0], {%1, %2, %3, %4};"
                     :: "l"(p), "f"(v.x), "f"(v.y), "f"(v.z), "f"(v.w)
                     : "memory");
    }
}

// ---------------------------------------------------------------------------
// Kernel 3: in-place ReLU on d_out
// ---------------------------------------------------------------------------
__global__ __launch_bounds__(256) void relu_kernel(float4* __restrict__ out, size_t n4)
{
    size_t i = (size_t)blockIdx.x * blockDim.x + threadIdx.x;
    size_t stride = (size_t)gridDim.x * blockDim.x;
    for (; i < n4; i += stride) {
        float4 v = out[i];
        v.x = fmaxf(v.x, 0.0f);
        v.y = fmaxf(v.y, 0.0f);
        v.z = fmaxf(v.z, 0.0f);
        v.w = fmaxf(v.w, 0.0f);
        out[i] = v;
    }
}

// ---------------------------------------------------------------------------
// Launch
// ---------------------------------------------------------------------------
extern "C" void kernel_launch(void* const* d_in, const int* in_sizes, int n_in,
                              void* d_out, int out_size)
{
    const float* h   = (const float*)d_in[0];
    const float* w   = (const float*)d_in[1];
    const float* ew  = (const float*)d_in[2];
    const int*   sv  = (const int*)d_in[3];
    const int*   dv  = (const int*)d_in[4];
    float* out       = (float*)d_out;

    const int M = in_sizes[0] / D;      // 100000
    const int E = in_sizes[2];          // 1600000

    static float* hp = nullptr;
    if (!hp) cudaGetSymbolAddress((void**)&hp, g_hp);

    cudaMemsetAsync(d_out, 0, (size_t)out_size * sizeof(float));

    // 1) hp = h @ W  (3xTF32 tensor-core GEMM)
    dim3 ggrid(D / 64, (M + 127) / 128);
    gemm_tf32_kernel<<<ggrid, 256>>>(h, w, hp, M);

    // 2) scatter-add: one warp per edge
    long long nthreads = (long long)E * 32;
    int sblocks = (int)((nthreads + 255) / 256);
    scatter_kernel<<<sblocks, 256>>>(hp, ew, sv, dv, out, E);

    // 3) ReLU in place
    size_t n4 = (size_t)out_size / 4;
    int rblocks = 148 * 12;
    relu_kernel<<<rblocks, 256>>>((float4*)out, n4);
}

// round 5
// speedup vs baseline: 2.0236x; 1.4850x over previous
#include <cuda_runtime.h>
#include <cuda_bf16.h>
#include <cstdint>

#define N_NODES 100000
#define N_EDGES_MAX 1600000
#define D 512

// Static device scratch
__device__ float g_hp[(size_t)N_NODES * D];       // projected features (204.8 MB)
__device__ int   g_cur[N_NODES];                  // degree counts -> cursors -> end offsets
__device__ int   g_off[N_NODES];                  // start offsets
__device__ int2  g_edge[N_EDGES_MAX];             // CSR-ordered (src, edge_weight-bits)

// ---------------------------------------------------------------------------
// tf32 helpers
// ---------------------------------------------------------------------------
__device__ __forceinline__ void split_tf32(float x, uint32_t& hi, uint32_t& lo)
{
    uint32_t xh = __float_as_uint(x) & 0xFFFFE000u;
    float fh = __uint_as_float(xh);
    float fl = x - fh;
    hi = xh;
    lo = __float_as_uint(fl) & 0xFFFFE000u;
}

__device__ __forceinline__ void mma_tf32(float c[4], const uint32_t a[4], const uint32_t b[2])
{
    asm volatile(
        "mma.sync.aligned.m16n8k8.row.col.f32.tf32.tf32.f32 "
        "{%0,%1,%2,%3}, {%4,%5,%6,%7}, {%8,%9}, {%0,%1,%2,%3};"
        : "+f"(c[0]), "+f"(c[1]), "+f"(c[2]), "+f"(c[3])
        : "r"(a[0]), "r"(a[1]), "r"(a[2]), "r"(a[3]), "r"(b[0]), "r"(b[1]));
}

#define CP_ASYNC16(dst_smem_u32, src_ptr) \
    asm volatile("cp.async.cg.shared.global [%0], [%1], 16;" \
                 :: "r"(dst_smem_u32), "l"(src_ptr))
#define CP_ASYNC_COMMIT() asm volatile("cp.async.commit_group;")
#define CP_ASYNC_WAIT0()  asm volatile("cp.async.wait_group 0;")

// ---------------------------------------------------------------------------
// Kernel 1: 3xTF32 tensor-core GEMM  hp[M,512] = h[M,512] @ W[512,512]
// (unchanged from round 4: tensor=71%, 726 us)
// ---------------------------------------------------------------------------
__global__ __launch_bounds__(256) void gemm_tf32_kernel(
    const float* __restrict__ h,
    const float* __restrict__ w,
    float* __restrict__ hp,
    int M)
{
    __shared__ float As[2][128][20];
    __shared__ float Bs[2][16][72];

    const int tid  = threadIdx.x;
    const int wid  = tid >> 5;
    const int lane = tid & 31;
    const int gid  = lane >> 2;
    const int tig  = lane & 3;

    const int warp_m = wid & 3;
    const int warp_n = wid >> 2;

    const int m0 = blockIdx.y * 128;
    const int n0 = blockIdx.x * 64;

    const int arow = tid >> 2;
    const int acol = (tid & 3) * 4;
    const int brow = tid >> 4;
    const int bcol = (tid & 15) * 4;

    const int gmA0 = min(m0 + arow,      M - 1);
    const int gmA1 = min(m0 + arow + 64, M - 1);

    auto load_tile = [&](int stage, int kt) {
        const int kbase = kt * 16;
        uint32_t d0 = (uint32_t)__cvta_generic_to_shared(&As[stage][arow][acol]);
        uint32_t d1 = (uint32_t)__cvta_generic_to_shared(&As[stage][arow + 64][acol]);
        CP_ASYNC16(d0, h + (size_t)gmA0 * D + kbase + acol);
        CP_ASYNC16(d1, h + (size_t)gmA1 * D + kbase + acol);
        uint32_t d2 = (uint32_t)__cvta_generic_to_shared(&Bs[stage][brow][bcol]);
        CP_ASYNC16(d2, w + (size_t)(kbase + brow) * D + n0 + bcol);
        CP_ASYNC_COMMIT();
    };

    float c[2][4][4];
    #pragma unroll
    for (int mi = 0; mi < 2; mi++)
        #pragma unroll
        for (int ni = 0; ni < 4; ni++)
            #pragma unroll
            for (int r = 0; r < 4; r++) c[mi][ni][r] = 0.0f;

    load_tile(0, 0);
    CP_ASYNC_WAIT0();
    __syncthreads();

    const int NK = D / 16;
    #pragma unroll 1
    for (int kt = 0; kt < NK; kt++) {
        const int s = kt & 1;
        if (kt + 1 < NK) load_tile(s ^ 1, kt + 1);

        #pragma unroll
        for (int ks = 0; ks < 2; ks++) {
            const int k0 = ks * 8;

            uint32_t ah[2][4], al[2][4];
            #pragma unroll
            for (int mi = 0; mi < 2; mi++) {
                const int mb = warp_m * 32 + mi * 16;
                float a0 = As[s][mb + gid    ][k0 + tig    ];
                float a1 = As[s][mb + gid + 8][k0 + tig    ];
                float a2 = As[s][mb + gid    ][k0 + tig + 4];
                float a3 = As[s][mb + gid + 8][k0 + tig + 4];
                split_tf32(a0, ah[mi][0], al[mi][0]);
                split_tf32(a1, ah[mi][1], al[mi][1]);
                split_tf32(a2, ah[mi][2], al[mi][2]);
                split_tf32(a3, ah[mi][3], al[mi][3]);
            }
            uint32_t bh[4][2], bl[4][2];
            #pragma unroll
            for (int ni = 0; ni < 4; ni++) {
                const int nb = warp_n * 32 + ni * 8;
                float b0 = Bs[s][k0 + tig    ][nb + gid];
                float b1 = Bs[s][k0 + tig + 4][nb + gid];
                split_tf32(b0, bh[ni][0], bl[ni][0]);
                split_tf32(b1, bh[ni][1], bl[ni][1]);
            }

            #pragma unroll
            for (int mi = 0; mi < 2; mi++)
                #pragma unroll
                for (int ni = 0; ni < 4; ni++) {
                    mma_tf32(c[mi][ni], ah[mi], bh[ni]);
                    mma_tf32(c[mi][ni], ah[mi], bl[ni]);
                    mma_tf32(c[mi][ni], al[mi], bh[ni]);
                }
        }

        CP_ASYNC_WAIT0();
        __syncthreads();
    }

    #pragma unroll
    for (int mi = 0; mi < 2; mi++) {
        #pragma unroll
        for (int ni = 0; ni < 4; ni++) {
            const int mrow = m0 + warp_m * 32 + mi * 16 + gid;
            const int ncol = n0 + warp_n * 32 + ni * 8 + tig * 2;
            if (mrow < M) {
                float2 v = make_float2(c[mi][ni][0], c[mi][ni][1]);
                *reinterpret_cast<float2*>(&hp[(size_t)mrow * D + ncol]) = v;
            }
            if (mrow + 8 < M) {
                float2 v = make_float2(c[mi][ni][2], c[mi][ni][3]);
                *reinterpret_cast<float2*>(&hp[(size_t)(mrow + 8) * D + ncol]) = v;
            }
        }
    }
}

// ---------------------------------------------------------------------------
// CSR build kernels
// ---------------------------------------------------------------------------
__global__ __launch_bounds__(256) void hist_kernel(const int* __restrict__ dst, int E)
{
    int i = blockIdx.x * blockDim.x + threadIdx.x;
    int stride = gridDim.x * blockDim.x;
    for (; i < E; i += stride)
        atomicAdd(&g_cur[dst[i]], 1);
}

// Single-block exclusive scan over g_cur[0..N) -> g_off (starts), g_cur := starts
__global__ __launch_bounds__(1024) void scan_kernel(int N)
{
    __shared__ int part[1024];
    const int t = threadIdx.x;
    const int chunk = (N + 1023) / 1024;
    const int begin = min(t * chunk, N);
    const int end   = min(begin + chunk, N);

    int sum = 0;
    for (int i = begin; i < end; i++) sum += g_cur[i];
    part[t] = sum;
    __syncthreads();

    // Hillis-Steele inclusive scan over 1024 partials
    #pragma unroll
    for (int s = 1; s < 1024; s <<= 1) {
        int v = (t >= s) ? part[t - s] : 0;
        __syncthreads();
        part[t] += v;
        __syncthreads();
    }

    int off = (t == 0) ? 0 : part[t - 1];   // exclusive prefix for this chunk
    for (int i = begin; i < end; i++) {
        int d = g_cur[i];
        g_off[i] = off;
        g_cur[i] = off;                     // cursor starts here
        off += d;
    }
}

__global__ __launch_bounds__(256) void bucket_kernel(
    const int* __restrict__ src,
    const int* __restrict__ dst,
    const float* __restrict__ ew,
    int E)
{
    int i = blockIdx.x * blockDim.x + threadIdx.x;
    int stride = gridDim.x * blockDim.x;
    for (; i < E; i += stride) {
        int d = dst[i];
        int p = atomicAdd(&g_cur[d], 1);
        g_edge[p] = make_int2(src[i], __float_as_int(ew[i]));
    }
}
// After bucket_kernel: g_cur[n] == end offset of node n's bucket.

// ---------------------------------------------------------------------------
// Kernel 4: per-node gather-aggregate + fused ReLU.
// One 128-thread block per node; thread t owns columns [4t, 4t+4).
// Two independent accumulator chains for MLP.
// ---------------------------------------------------------------------------
__global__ __launch_bounds__(128) void aggregate_kernel(
    const float* __restrict__ hp,
    float* __restrict__ out,
    int N)
{
    const int n = blockIdx.x;
    if (n >= N) return;
    const int t = threadIdx.x;
    const int col = t * 4;

    int j  = g_off[n];
    const int je = g_cur[n];

    float4 acc0 = make_float4(0.f, 0.f, 0.f, 0.f);
    float4 acc1 = make_float4(0.f, 0.f, 0.f, 0.f);

    for (; j + 1 < je; j += 2) {
        int2 e0 = __ldg(&g_edge[j]);
        int2 e1 = __ldg(&g_edge[j + 1]);
        float w0 = __int_as_float(e0.y);
        float w1 = __int_as_float(e1.y);
        float4 v0 = *reinterpret_cast<const float4*>(hp + (size_t)e0.x * D + col);
        float4 v1 = *reinterpret_cast<const float4*>(hp + (size_t)e1.x * D + col);
        acc0.x += w0 * v0.x; acc0.y += w0 * v0.y; acc0.z += w0 * v0.z; acc0.w += w0 * v0.w;
        acc1.x += w1 * v1.x; acc1.y += w1 * v1.y; acc1.z += w1 * v1.z; acc1.w += w1 * v1.w;
    }
    if (j < je) {
        int2 e0 = __ldg(&g_edge[j]);
        float w0 = __int_as_float(e0.y);
        float4 v0 = *reinterpret_cast<const float4*>(hp + (size_t)e0.x * D + col);
        acc0.x += w0 * v0.x; acc0.y += w0 * v0.y; acc0.z += w0 * v0.z; acc0.w += w0 * v0.w;
    }

    float4 r;
    r.x = fmaxf(acc0.x + acc1.x, 0.f);
    r.y = fmaxf(acc0.y + acc1.y, 0.f);
    r.z = fmaxf(acc0.z + acc1.z, 0.f);
    r.w = fmaxf(acc0.w + acc1.w, 0.f);
    *reinterpret_cast<float4*>(out + (size_t)n * D + col) = r;
}

// ---------------------------------------------------------------------------
// Launch
// Inputs: h [N*512] f32, weight [512*512] f32, edge_weight [E] f32,
//         src [E] i32, dst [E] i32.  Output: [N*512] f32
// ---------------------------------------------------------------------------
extern "C" void kernel_launch(void* const* d_in, const int* in_sizes, int n_in,
                              void* d_out, int out_size)
{
    const float* h   = (const float*)d_in[0];
    const float* w   = (const float*)d_in[1];
    const float* ew  = (const float*)d_in[2];
    const int*   sv  = (const int*)d_in[3];
    const int*   dv  = (const int*)d_in[4];
    float* out       = (float*)d_out;

    const int M = in_sizes[0] / D;      // 100000
    const int E = in_sizes[2];          // 1600000

    static float* hp  = nullptr;
    static int*   cur = nullptr;
    if (!hp)  cudaGetSymbolAddress((void**)&hp,  g_hp);
    if (!cur) cudaGetSymbolAddress((void**)&cur, g_cur);

    // 0) zero degree counters
    cudaMemsetAsync(cur, 0, (size_t)M * sizeof(int));

    // 1) hp = h @ W  (3xTF32 tensor-core GEMM)
    dim3 ggrid(D / 64, (M + 127) / 128);
    gemm_tf32_kernel<<<ggrid, 256>>>(h, w, hp, M);

    // 2) CSR build: histogram -> scan -> bucket
    int eblocks = min((E + 255) / 256, 148 * 8);
    hist_kernel<<<eblocks, 256>>>(dv, E);
    scan_kernel<<<1, 1024>>>(M);
    bucket_kernel<<<eblocks, 256>>>(sv, dv, ew, E);

    // 3) gather-aggregate + fused ReLU (no atomics, no memset of out)
    aggregate_kernel<<<M, 128>>>(hp, out, M);
}

// round 6
// speedup vs baseline: 2.1606x; 1.0677x over previous
#include <cuda_runtime.h>
#include <cuda_bf16.h>
#include <cstdint>

#define N_NODES 100000
#define N_EDGES_MAX 1600000
#define D 512

// Static device scratch
__device__ float g_hp[(size_t)N_NODES * D];       // projected features (204.8 MB)
__device__ int   g_cur[N_NODES];                  // degree counts -> cursors -> end offsets
__device__ int   g_off[N_NODES];                  // start offsets
__device__ int2  g_edge[N_EDGES_MAX];             // CSR-ordered (src, edge_weight-bits)

// ---------------------------------------------------------------------------
// bf16 split helpers: x = hi + lo (both bf16), residual ~2^-17 |x|
// Packs two consecutive-k values into one .b32 (low half = first k).
// ---------------------------------------------------------------------------
__device__ __forceinline__ void split_bf16x2(float x0, float x1, uint32_t& hi, uint32_t& lo)
{
    __nv_bfloat162 h = __floats2bfloat162_rn(x0, x1);
    float r0 = x0 - __bfloat162float(h.x);
    float r1 = x1 - __bfloat162float(h.y);
    __nv_bfloat162 l = __floats2bfloat162_rn(r0, r1);
    hi = reinterpret_cast<uint32_t&>(h);
    lo = reinterpret_cast<uint32_t&>(l);
}

__device__ __forceinline__ void mma_bf16(float c[4], const uint32_t a[4], const uint32_t b[2])
{
    asm volatile(
        "mma.sync.aligned.m16n8k16.row.col.f32.bf16.bf16.f32 "
        "{%0,%1,%2,%3}, {%4,%5,%6,%7}, {%8,%9}, {%0,%1,%2,%3};"
        : "+f"(c[0]), "+f"(c[1]), "+f"(c[2]), "+f"(c[3])
        : "r"(a[0]), "r"(a[1]), "r"(a[2]), "r"(a[3]), "r"(b[0]), "r"(b[1]));
}

#define CP_ASYNC16(dst_smem_u32, src_ptr) \
    asm volatile("cp.async.cg.shared.global [%0], [%1], 16;" \
                 :: "r"(dst_smem_u32), "l"(src_ptr))
#define CP_ASYNC_COMMIT() asm volatile("cp.async.commit_group;")
#define CP_ASYNC_WAIT0()  asm volatile("cp.async.wait_group 0;")

// ---------------------------------------------------------------------------
// Kernel 1: 3x-BF16 tensor-core GEMM  hp[M,512] = h[M,512] @ W[512,512]
// BM=128, BN=64, BK=16. 8 warps (4x2), warp tile 32x32, m16n8k16 fragments.
// A stride 24 (float2 frag loads conflict-free), B stride 68 (scalar octets).
// ---------------------------------------------------------------------------
__global__ __launch_bounds__(256) void gemm_bf16x3_kernel(
    const float* __restrict__ h,
    const float* __restrict__ w,
    float* __restrict__ hp,
    int M)
{
    __shared__ float As[2][128][24];
    __shared__ float Bs[2][16][68];

    const int tid  = threadIdx.x;
    const int wid  = tid >> 5;
    const int lane = tid & 31;
    const int gid  = lane >> 2;     // 0..7
    const int tig  = lane & 3;      // 0..3

    const int warp_m = wid & 3;
    const int warp_n = wid >> 2;

    const int m0 = blockIdx.y * 128;
    const int n0 = blockIdx.x * 64;

    const int arow = tid >> 2;          // 0..63
    const int acol = (tid & 3) * 4;     // 0,4,8,12
    const int brow = tid >> 4;          // 0..15
    const int bcol = (tid & 15) * 4;    // 0..60

    const int gmA0 = min(m0 + arow,      M - 1);
    const int gmA1 = min(m0 + arow + 64, M - 1);

    auto load_tile = [&](int stage, int kt) {
        const int kbase = kt * 16;
        uint32_t d0 = (uint32_t)__cvta_generic_to_shared(&As[stage][arow][acol]);
        uint32_t d1 = (uint32_t)__cvta_generic_to_shared(&As[stage][arow + 64][acol]);
        CP_ASYNC16(d0, h + (size_t)gmA0 * D + kbase + acol);
        CP_ASYNC16(d1, h + (size_t)gmA1 * D + kbase + acol);
        uint32_t d2 = (uint32_t)__cvta_generic_to_shared(&Bs[stage][brow][bcol]);
        CP_ASYNC16(d2, w + (size_t)(kbase + brow) * D + n0 + bcol);
        CP_ASYNC_COMMIT();
    };

    float c[2][4][4];
    #pragma unroll
    for (int mi = 0; mi < 2; mi++)
        #pragma unroll
        for (int ni = 0; ni < 4; ni++)
            #pragma unroll
            for (int r = 0; r < 4; r++) c[mi][ni][r] = 0.0f;

    load_tile(0, 0);
    CP_ASYNC_WAIT0();
    __syncthreads();

    const int NK = D / 16;   // 32
    #pragma unroll 1
    for (int kt = 0; kt < NK; kt++) {
        const int s = kt & 1;
        if (kt + 1 < NK) load_tile(s ^ 1, kt + 1);

        // --- A fragments (m16n8k16): regs hold k-pairs ---
        // a0:(row gid,   k 2tig/2tig+1)  a1:(row gid+8, same)
        // a2:(row gid,   k 2tig+8/+9)    a3:(row gid+8, same)
        uint32_t ah[2][4], al[2][4];
        #pragma unroll
        for (int mi = 0; mi < 2; mi++) {
            const int mb = warp_m * 32 + mi * 16;
            float2 f0 = *reinterpret_cast<const float2*>(&As[s][mb + gid    ][2 * tig    ]);
            float2 f1 = *reinterpret_cast<const float2*>(&As[s][mb + gid + 8][2 * tig    ]);
            float2 f2 = *reinterpret_cast<const float2*>(&As[s][mb + gid    ][2 * tig + 8]);
            float2 f3 = *reinterpret_cast<const float2*>(&As[s][mb + gid + 8][2 * tig + 8]);
            split_bf16x2(f0.x, f0.y, ah[mi][0], al[mi][0]);
            split_bf16x2(f1.x, f1.y, ah[mi][1], al[mi][1]);
            split_bf16x2(f2.x, f2.y, ah[mi][2], al[mi][2]);
            split_bf16x2(f3.x, f3.y, ah[mi][3], al[mi][3]);
        }
        // --- B fragments: b0:(k 2tig/2tig+1, col gid), b1:(k 2tig+8/+9) ---
        uint32_t bh[4][2], bl[4][2];
        #pragma unroll
        for (int ni = 0; ni < 4; ni++) {
            const int cb = warp_n * 32 + ni * 8 + gid;
            float v0 = Bs[s][2 * tig    ][cb];
            float v1 = Bs[s][2 * tig + 1][cb];
            float v2 = Bs[s][2 * tig + 8][cb];
            float v3 = Bs[s][2 * tig + 9][cb];
            split_bf16x2(v0, v1, bh[ni][0], bl[ni][0]);
            split_bf16x2(v2, v3, bh[ni][1], bl[ni][1]);
        }

        #pragma unroll
        for (int mi = 0; mi < 2; mi++)
            #pragma unroll
            for (int ni = 0; ni < 4; ni++) {
                mma_bf16(c[mi][ni], ah[mi], bh[ni]);   // hi*hi
                mma_bf16(c[mi][ni], ah[mi], bl[ni]);   // hi*lo
                mma_bf16(c[mi][ni], al[mi], bh[ni]);   // lo*hi
            }

        CP_ASYNC_WAIT0();
        __syncthreads();
    }

    // Epilogue: C frag (16x8): c0 (gid, 2tig), c1 (gid, 2tig+1),
    //                          c2 (gid+8, 2tig), c3 (gid+8, 2tig+1)
    #pragma unroll
    for (int mi = 0; mi < 2; mi++) {
        #pragma unroll
        for (int ni = 0; ni < 4; ni++) {
            const int mrow = m0 + warp_m * 32 + mi * 16 + gid;
            const int ncol = n0 + warp_n * 32 + ni * 8 + tig * 2;
            if (mrow < M) {
                float2 v = make_float2(c[mi][ni][0], c[mi][ni][1]);
                *reinterpret_cast<float2*>(&hp[(size_t)mrow * D + ncol]) = v;
            }
            if (mrow + 8 < M) {
                float2 v = make_float2(c[mi][ni][2], c[mi][ni][3]);
                *reinterpret_cast<float2*>(&hp[(size_t)(mrow + 8) * D + ncol]) = v;
            }
        }
    }
}

// ---------------------------------------------------------------------------
// CSR build kernels
// ---------------------------------------------------------------------------
__global__ __launch_bounds__(256) void hist_kernel(const int* __restrict__ dst, int E)
{
    int i = blockIdx.x * blockDim.x + threadIdx.x;
    int stride = gridDim.x * blockDim.x;
    for (; i < E; i += stride)
        atomicAdd(&g_cur[dst[i]], 1);
}

__global__ __launch_bounds__(1024) void scan_kernel(int N)
{
    __shared__ int part[1024];
    const int t = threadIdx.x;
    const int chunk = (N + 1023) / 1024;
    const int begin = min(t * chunk, N);
    const int end   = min(begin + chunk, N);

    int sum = 0;
    for (int i = begin; i < end; i++) sum += g_cur[i];
    part[t] = sum;
    __syncthreads();

    #pragma unroll
    for (int s = 1; s < 1024; s <<= 1) {
        int v = (t >= s) ? part[t - s] : 0;
        __syncthreads();
        part[t] += v;
        __syncthreads();
    }

    int off = (t == 0) ? 0 : part[t - 1];
    for (int i = begin; i < end; i++) {
        int d = g_cur[i];
        g_off[i] = off;
        g_cur[i] = off;
        off += d;
    }
}

__global__ __launch_bounds__(256) void bucket_kernel(
    const int* __restrict__ src,
    const int* __restrict__ dst,
    const float* __restrict__ ew,
    int E)
{
    int i = blockIdx.x * blockDim.x + threadIdx.x;
    int stride = gridDim.x * blockDim.x;
    for (; i < E; i += stride) {
        int d = dst[i];
        int p = atomicAdd(&g_cur[d], 1);
        g_edge[p] = make_int2(src[i], __float_as_int(ew[i]));
    }
}

// ---------------------------------------------------------------------------
// Kernel 4: per-node gather-aggregate + fused ReLU.
// ---------------------------------------------------------------------------
__global__ __launch_bounds__(128) void aggregate_kernel(
    const float* __restrict__ hp,
    float* __restrict__ out,
    int N)
{
    const int n = blockIdx.x;
    if (n >= N) return;
    const int t = threadIdx.x;
    const int col = t * 4;

    int j  = g_off[n];
    const int je = g_cur[n];

    float4 acc0 = make_float4(0.f, 0.f, 0.f, 0.f);
    float4 acc1 = make_float4(0.f, 0.f, 0.f, 0.f);

    for (; j + 1 < je; j += 2) {
        int2 e0 = __ldg(&g_edge[j]);
        int2 e1 = __ldg(&g_edge[j + 1]);
        float w0 = __int_as_float(e0.y);
        float w1 = __int_as_float(e1.y);
        float4 v0 = *reinterpret_cast<const float4*>(hp + (size_t)e0.x * D + col);
        float4 v1 = *reinterpret_cast<const float4*>(hp + (size_t)e1.x * D + col);
        acc0.x += w0 * v0.x; acc0.y += w0 * v0.y; acc0.z += w0 * v0.z; acc0.w += w0 * v0.w;
        acc1.x += w1 * v1.x; acc1.y += w1 * v1.y; acc1.z += w1 * v1.z; acc1.w += w1 * v1.w;
    }
    if (j < je) {
        int2 e0 = __ldg(&g_edge[j]);
        float w0 = __int_as_float(e0.y);
        float4 v0 = *reinterpret_cast<const float4*>(hp + (size_t)e0.x * D + col);
        acc0.x += w0 * v0.x; acc0.y += w0 * v0.y; acc0.z += w0 * v0.z; acc0.w += w0 * v0.w;
    }

    float4 r;
    r.x = fmaxf(acc0.x + acc1.x, 0.f);
    r.y = fmaxf(acc0.y + acc1.y, 0.f);
    r.z = fmaxf(acc0.z + acc1.z, 0.f);
    r.w = fmaxf(acc0.w + acc1.w, 0.f);
    *reinterpret_cast<float4*>(out + (size_t)n * D + col) = r;
}

// ---------------------------------------------------------------------------
// Launch
// ---------------------------------------------------------------------------
extern "C" void kernel_launch(void* const* d_in, const int* in_sizes, int n_in,
                              void* d_out, int out_size)
{
    const float* h   = (const float*)d_in[0];
    const float* w   = (const float*)d_in[1];
    const float* ew  = (const float*)d_in[2];
    const int*   sv  = (const int*)d_in[3];
    const int*   dv  = (const int*)d_in[4];
    float* out       = (float*)d_out;

    const int M = in_sizes[0] / D;      // 100000
    const int E = in_sizes[2];          // 1600000

    static float* hp  = nullptr;
    static int*   cur = nullptr;
    if (!hp)  cudaGetSymbolAddress((void**)&hp,  g_hp);
    if (!cur) cudaGetSymbolAddress((void**)&cur, g_cur);

    // 0) zero degree counters
    cudaMemsetAsync(cur, 0, (size_t)M * sizeof(int));

    // 1) hp = h @ W  (3x-BF16 tensor-core GEMM)
    dim3 ggrid(D / 64, (M + 127) / 128);
    gemm_bf16x3_kernel<<<ggrid, 256>>>(h, w, hp, M);

    // 2) CSR build: histogram -> scan -> bucket
    int eblocks = min((E + 255) / 256, 148 * 8);
    hist_kernel<<<eblocks, 256>>>(dv, E);
    scan_kernel<<<1, 1024>>>(M);
    bucket_kernel<<<eblocks, 256>>>(sv, dv, ew, E);

    // 3) gather-aggregate + fused ReLU
    aggregate_kernel<<<M, 128>>>(hp, out, M);
}